// round 5
// baseline (speedup 1.0000x reference)
#include <cuda_runtime.h>
#include <cstdint>

#define CAPS 32
#define FEAT 256
#define TMA_CAPS 24
#define LDG_CAPS 8
#define ROW_ELEMS (CAPS * FEAT)
#define SLOT_BYTES (TMA_CAPS * FEAT * 4)          // 24576
#define NBUF 4
#define SMEM_BYTES (NBUF * SLOT_BYTES + NBUF * 8) // 4 slots + 4 mbarriers

extern __shared__ unsigned char smem_raw[];

__device__ __forceinline__ uint32_t smem_u32(const void* p) {
    uint32_t a;
    asm("{ .reg .u64 t; cvta.to.shared.u64 t, %1; cvt.u32.u64 %0, t; }"
        : "=r"(a) : "l"(p));
    return a;
}

__device__ __forceinline__ void mbar_init(uint32_t addr, uint32_t count) {
    asm volatile("mbarrier.init.shared::cta.b64 [%0], %1;"
                 :: "r"(addr), "r"(count) : "memory");
}

__device__ __forceinline__ void mbar_expect_tx(uint32_t addr, uint32_t bytes) {
    asm volatile("mbarrier.arrive.expect_tx.shared::cta.b64 _, [%0], %1;"
                 :: "r"(addr), "r"(bytes) : "memory");
}

__device__ __forceinline__ void bulk_copy_g2s(uint32_t dst, const void* src,
                                              uint32_t bytes, uint32_t mbar) {
    asm volatile(
        "cp.async.bulk.shared::cta.global.mbarrier::complete_tx::bytes "
        "[%0], [%1], %2, [%3];"
        :: "r"(dst), "l"(src), "r"(bytes), "r"(mbar) : "memory");
}

__device__ __forceinline__ void mbar_wait(uint32_t addr, uint32_t parity) {
    asm volatile(
        "{\n\t"
        ".reg .pred P;\n"
        "WAIT_%=:\n\t"
        "mbarrier.try_wait.parity.acquire.cta.shared::cta.b64 P, [%0], %1, 10000000;\n\t"
        "@!P bra WAIT_%=;\n\t"
        "}"
        :: "r"(addr), "r"(parity) : "memory");
}

__global__ __launch_bounds__(256, 2)
void router_kernel(const float* __restrict__ x,
                   const float* __restrict__ bias,
                   float* __restrict__ out, int B)
{
    __shared__ float warp_part[8][32];

    const int tid  = threadIdx.x;       // feature column j = tid
    const int lane = tid & 31;
    const int wid  = tid >> 5;
    const int grid = gridDim.x;

    const uint32_t buf_s0    = smem_u32(smem_raw);
    const uint32_t mbar_base = smem_u32(smem_raw + NBUF * SLOT_BYTES);

    if (tid == 0) {
#pragma unroll
        for (int s = 0; s < NBUF; s++) mbar_init(mbar_base + s * 8, 1);
    }
    __syncthreads();

    // bias column j in registers, loaded once per CTA (persistent grid)
    float breg[CAPS];
#pragma unroll
    for (int i = 0; i < CAPS; i++) breg[i] = bias[i * FEAT + tid];

    // Prologue: TMA slots 0..2 (caps 0..23 of rows b0, b0+g, b0+2g)
    if (tid == 0) {
#pragma unroll
        for (int s = 0; s < 3; s++) {
            const int pb = blockIdx.x + s * grid;
            if (pb < B) {
                mbar_expect_tx(mbar_base + s * 8, SLOT_BYTES);
                bulk_copy_g2s(buf_s0 + s * SLOT_BYTES,
                              x + (size_t)pb * ROW_ELEMS,
                              SLOT_BYTES, mbar_base + s * 8);
            }
        }
    }

    // Prologue: LDG caps 24..31 of the first row into registers
    float ldg8[LDG_CAPS];
    if (blockIdx.x < B) {
        const float* xr = x + (size_t)blockIdx.x * ROW_ELEMS + TMA_CAPS * FEAT + tid;
#pragma unroll
        for (int k = 0; k < LDG_CAPS; k++) ldg8[k] = __ldcs(xr + k * FEAT);
    }

    uint32_t phase[NBUF] = { 0, 0, 0, 0 };  // constant-indexed -> registers

    for (int b0 = blockIdx.x; b0 < B; b0 += NBUF * grid) {
#pragma unroll
        for (int s = 0; s < NBUF; s++) {
            const int b = b0 + s * grid;
            if (b >= B) continue;

            // Issue TMA 3 iterations ahead into slot (s+3)%4 (compile-time).
            // That slot was last read before the __syncthreads of iteration
            // it-1, which thread 0 has already passed -> free.
            const int ns = (s + 3) % NBUF;
            const int nb3 = b + 3 * grid;
            if (nb3 < B && tid == 0) {
                mbar_expect_tx(mbar_base + ns * 8, SLOT_BYTES);
                bulk_copy_g2s(buf_s0 + ns * SLOT_BYTES,
                              x + (size_t)nb3 * ROW_ELEMS,
                              SLOT_BYTES, mbar_base + ns * 8);
            }

            // Wait for this row's TMA (caps 0..23)
            mbar_wait(mbar_base + s * 8, phase[s]);
            phase[s] ^= 1;

            // Assemble column j: caps 0..23 from smem, 24..31 from LDG regs
            const float* bp = (const float*)(smem_raw + s * SLOT_BYTES) + tid;
            float xv[CAPS];
#pragma unroll
            for (int i = 0; i < TMA_CAPS; i++) xv[i] = bp[i * FEAT];
#pragma unroll
            for (int k = 0; k < LDG_CAPS; k++) xv[TMA_CAPS + k] = ldg8[k];

            // Prefetch next row's caps 24..31 (consumed next iteration,
            // ~full row-period of latency cover)
            const int nb1 = b + grid;
            if (nb1 < B) {
                const float* xr = x + (size_t)nb1 * ROW_ELEMS + TMA_CAPS * FEAT + tid;
#pragma unroll
                for (int k = 0; k < LDG_CAPS; k++) ldg8[k] = __ldcs(xr + k * FEAT);
            }

            // t[j] = sum_i x[b,i,j]
            float t = 0.f;
#pragma unroll
            for (int i = 0; i < CAPS; i++) t += xv[i];

            // p[i] = x[b,i,j] * t[j]
            float p[CAPS];
#pragma unroll
            for (int i = 0; i < CAPS; i++) p[i] = xv[i] * t;

            // Warp transpose-reduce: lane l ends with this warp's
            // 32-feature partial of score[l].
#pragma unroll
            for (int d = 16; d >= 1; d >>= 1) {
                const bool up = (lane & d) != 0;
#pragma unroll
                for (int k = 0; k < d; k++) {
                    float send = up ? p[k] : p[k + d];
                    float recv = __shfl_xor_sync(0xffffffffu, send, d);
                    p[k] = (up ? p[k + d] : p[k]) + recv;
                }
            }
            warp_part[wid][lane] = p[0];
            __syncthreads();

            // All warps redundantly compute the 32-wide softmax.
            float sc = 0.f;
#pragma unroll
            for (int w = 0; w < 8; w++) sc += warp_part[w][lane];
            sc *= (1.0f / 16.0f);            // 1/sqrt(FEAT)

            float m = sc;
#pragma unroll
            for (int d = 16; d >= 1; d >>= 1)
                m = fmaxf(m, __shfl_xor_sync(0xffffffffu, m, d));
            float e = __expf(sc - m);
            float sum = e;
#pragma unroll
            for (int d = 16; d >= 1; d >>= 1)
                sum += __shfl_xor_sync(0xffffffffu, sum, d);
            const float attn_lane = e / sum;

            // out[b,j] = sum_i x[b,i,j] * (attn[i] + bias[i,j])
            float acc = 0.f;
#pragma unroll
            for (int i = 0; i < CAPS; i++) {
                const float ai = __shfl_sync(0xffffffffu, attn_lane, i);
                acc = fmaf(xv[i], ai + breg[i], acc);
            }
            out[(size_t)b * FEAT + tid] = acc;
        }
    }
}

extern "C" void kernel_launch(void* const* d_in, const int* in_sizes, int n_in,
                              void* d_out, int out_size)
{
    const float* x    = (const float*)d_in[0];   // inputs [B, 32, 256] fp32
    const float* bias = (const float*)d_in[1];   // bias   [32, 256]   fp32
    float* out        = (float*)d_out;           // out    [B, 256]    fp32

    const int B = in_sizes[0] / (CAPS * FEAT);

    cudaFuncSetAttribute(router_kernel,
                         cudaFuncAttributeMaxDynamicSharedMemorySize,
                         SMEM_BYTES);

    int grid = 304;                    // 2 persistent CTAs per SM (152 SMs)
    if (grid > B) grid = B;
    router_kernel<<<grid, 256, SMEM_BYTES>>>(x, bias, out, B);
}

// round 6
// speedup vs baseline: 1.0274x; 1.0274x over previous
#include <cuda_runtime.h>
#include <cstdint>

#define CAPS 32
#define FEAT 256
#define ROW_BYTES (CAPS * FEAT * 4)        // 32768
#define NBUF 3
#define SMEM_BYTES (NBUF * ROW_BYTES + NBUF * 8)   // 3 row buffers + 3 mbarriers

extern __shared__ unsigned char smem_raw[];

__device__ __forceinline__ uint32_t smem_u32(const void* p) {
    uint32_t a;
    asm("{ .reg .u64 t; cvta.to.shared.u64 t, %1; cvt.u32.u64 %0, t; }"
        : "=r"(a) : "l"(p));
    return a;
}

__device__ __forceinline__ void mbar_init(uint32_t addr, uint32_t count) {
    asm volatile("mbarrier.init.shared::cta.b64 [%0], %1;"
                 :: "r"(addr), "r"(count) : "memory");
}

__device__ __forceinline__ void mbar_expect_tx(uint32_t addr, uint32_t bytes) {
    asm volatile("mbarrier.arrive.expect_tx.shared::cta.b64 _, [%0], %1;"
                 :: "r"(addr), "r"(bytes) : "memory");
}

__device__ __forceinline__ void bulk_copy_g2s(uint32_t dst, const void* src,
                                              uint32_t bytes, uint32_t mbar) {
    asm volatile(
        "cp.async.bulk.shared::cta.global.mbarrier::complete_tx::bytes "
        "[%0], [%1], %2, [%3];"
        :: "r"(dst), "l"(src), "r"(bytes), "r"(mbar) : "memory");
}

__device__ __forceinline__ void mbar_wait(uint32_t addr, uint32_t parity) {
    asm volatile(
        "{\n\t"
        ".reg .pred P;\n"
        "WAIT_%=:\n\t"
        "mbarrier.try_wait.parity.acquire.cta.shared::cta.b64 P, [%0], %1, 10000000;\n\t"
        "@!P bra WAIT_%=;\n\t"
        "}"
        :: "r"(addr), "r"(parity) : "memory");
}

__global__ __launch_bounds__(256, 2)
void router_kernel(const float* __restrict__ x,
                   const float* __restrict__ bias,
                   float* __restrict__ out, int B)
{
    __shared__ float warp_part[8][32];
    __shared__ float attn8[8][32];      // per-warp private attn row

    const int tid  = threadIdx.x;       // feature column j = tid
    const int lane = tid & 31;
    const int wid  = tid >> 5;
    const int grid = gridDim.x;

    const uint32_t buf_s0    = smem_u32(smem_raw);
    const uint32_t mbar_base = smem_u32(smem_raw + NBUF * ROW_BYTES);

    if (tid == 0) {
#pragma unroll
        for (int s = 0; s < NBUF; s++) mbar_init(mbar_base + s * 8, 1);
    }
    __syncthreads();

    // bias column j in registers, loaded once per CTA (persistent grid)
    float breg[CAPS];
#pragma unroll
    for (int i = 0; i < CAPS; i++) breg[i] = bias[i * FEAT + tid];

    // Prologue: prefetch rows for slots 0 and 1 (2-deep lookahead)
    if (tid == 0) {
#pragma unroll
        for (int s = 0; s < 2; s++) {
            const int pb = blockIdx.x + s * grid;
            if (pb < B) {
                mbar_expect_tx(mbar_base + s * 8, ROW_BYTES);
                bulk_copy_g2s(buf_s0 + s * ROW_BYTES,
                              x + (size_t)pb * (CAPS * FEAT),
                              ROW_BYTES, mbar_base + s * 8);
            }
        }
    }

    uint32_t phase[NBUF] = { 0, 0, 0 };   // constant-indexed only -> registers

    for (int b0 = blockIdx.x; b0 < B; b0 += NBUF * grid) {
#pragma unroll
        for (int s = 0; s < NBUF; s++) {
            const int b = b0 + s * grid;
            if (b >= B) continue;

            // Issue prefetch 2 ahead into slot (s+2)%3 BEFORE waiting on the
            // current slot. Target slot was last read before the
            // __syncthreads of iteration it-1, already passed by thread 0.
            const int ns = (s + 2) % NBUF;     // compile-time constant
            const int nb = b + 2 * grid;
            if (nb < B && tid == 0) {
                mbar_expect_tx(mbar_base + ns * 8, ROW_BYTES);
                bulk_copy_g2s(buf_s0 + ns * ROW_BYTES,
                              x + (size_t)nb * (CAPS * FEAT),
                              ROW_BYTES, mbar_base + ns * 8);
            }

            // Wait for this row's DMA
            mbar_wait(mbar_base + s * 8, phase[s]);
            phase[s] ^= 1;

            // Read column j of the row from smem: x[b, i, j], i = 0..31
            const float* bp = (const float*)(smem_raw + s * ROW_BYTES) + tid;
            float xv[CAPS];
#pragma unroll
            for (int i = 0; i < CAPS; i++) xv[i] = bp[i * FEAT];

            // t[j] = sum_i x[b,i,j]
            float t = 0.f;
#pragma unroll
            for (int i = 0; i < CAPS; i++) t += xv[i];

            // p[i] = x[b,i,j] * t[j]
            float p[CAPS];
#pragma unroll
            for (int i = 0; i < CAPS; i++) p[i] = xv[i] * t;

            // Warp transpose-reduce: 31 SHFLs; lane l ends with this warp's
            // 32-feature partial of score[l].
#pragma unroll
            for (int d = 16; d >= 1; d >>= 1) {
                const bool up = (lane & d) != 0;
#pragma unroll
                for (int k = 0; k < d; k++) {
                    float send = up ? p[k] : p[k + d];
                    float recv = __shfl_xor_sync(0xffffffffu, send, d);
                    p[k] = (up ? p[k + d] : p[k]) + recv;
                }
            }
            warp_part[wid][lane] = p[0];
            __syncthreads();

            // All warps redundantly compute the 32-wide softmax (keeps the
            // single-barrier structure).
            float sc = 0.f;
#pragma unroll
            for (int w = 0; w < 8; w++) sc += warp_part[w][lane];
            sc *= (1.0f / 16.0f);            // 1/sqrt(FEAT)

            float m = sc;
#pragma unroll
            for (int d = 16; d >= 1; d >>= 1)
                m = fmaxf(m, __shfl_xor_sync(0xffffffffu, m, d));
            float e = __expf(sc - m);
            float sum = e;
#pragma unroll
            for (int d = 16; d >= 1; d >>= 1)
                sum += __shfl_xor_sync(0xffffffffu, sum, d);

            // Publish attn to this warp's private smem row; broadcast LDS
            // replaces 32 SHFLs (LDS broadcast = 1 conflict-free wavefront).
            attn8[wid][lane] = e / sum;
            __syncwarp();

            // out[b,j] = sum_i x[b,i,j] * (attn[i] + bias[i,j])
            const float* arow = attn8[wid];
            float acc = 0.f;
#pragma unroll
            for (int i = 0; i < CAPS; i++)
                acc = fmaf(xv[i], arow[i] + breg[i], acc);
            out[(size_t)b * FEAT + tid] = acc;
        }
    }
}

extern "C" void kernel_launch(void* const* d_in, const int* in_sizes, int n_in,
                              void* d_out, int out_size)
{
    const float* x    = (const float*)d_in[0];   // inputs [B, 32, 256] fp32
    const float* bias = (const float*)d_in[1];   // bias   [32, 256]   fp32
    float* out        = (float*)d_out;           // out    [B, 256]    fp32

    const int B = in_sizes[0] / (CAPS * FEAT);

    cudaFuncSetAttribute(router_kernel,
                         cudaFuncAttributeMaxDynamicSharedMemorySize,
                         SMEM_BYTES);

    int grid = 304;                    // 2 persistent CTAs per SM (152 SMs)
    if (grid > B) grid = B;
    router_kernel<<<grid, 256, SMEM_BYTES>>>(x, bias, out, B);
}